// round 9
// baseline (speedup 1.0000x reference)
#include <cuda_runtime.h>
#include <math.h>

#define NB      148              // one block per SM, single wave
#define NTHR    384              // 12 warps; 170 regs/thread budget
#define GPB     (NTHR / 4)       // 96 groups (4 lanes each) per block
#define NGROUPS (NB * GPB)       // 14208
#define NWARP   (NTHR / 32)      // 12

typedef unsigned long long ull;

// Per-block partials: [block][head][ s, acc[64] ]  (fixed softmax base = 0;
// per-head constant score offset cancels in A/S -> dropped entirely)
__device__ float g_part[NB][4][65];
__device__ unsigned g_done = 0;

// ---- packed f32x2 helpers (ptxas never auto-fuses FFMA2) --------------------
__device__ __forceinline__ ull pk2(float lo, float hi) {
    ull r; asm("mov.b64 %0,{%1,%2};" : "=l"(r) : "f"(lo), "f"(hi)); return r;
}
__device__ __forceinline__ void upk2(float& lo, float& hi, ull p) {
    asm("mov.b64 {%0,%1},%2;" : "=f"(lo), "=f"(hi) : "l"(p));
}
__device__ __forceinline__ ull fma2(ull a, ull b, ull c) {
    ull d; asm("fma.rn.f32x2 %0,%1,%2,%3;" : "=l"(d) : "l"(a), "l"(b), "l"(c)); return d;
}
__device__ __forceinline__ float tanh_ap(float x) {
    float y; asm("tanh.approx.f32 %0,%1;" : "=f"(y) : "f"(x)); return y;
}
__device__ __forceinline__ float ex2_ap(float x) {
    float y; asm("ex2.approx.f32 %0,%1;" : "=f"(y) : "f"(x)); return y;
}
// silu(x) = h + h*tanh(h) with h = x/2 (the 1/2 is pre-folded into W1/b1)
__device__ __forceinline__ ull silu2h(ull hpk) {
    float h0, h1; upk2(h0, h1, hpk);
    ull tpk = pk2(tanh_ap(h0), tanh_ap(h1));
    return fma2(hpk, tpk, hpk);
}

// -----------------------------------------------------------------------------
// Single fused kernel, 4 lanes per point (each lane owns 16 dims = 8 pairs):
// inline prep -> branch-free streaming exp-accumulate (next point prefetched,
// u-table streamed from conflict-free shared) -> block partial -> last block
// does final combine + projections.
// -----------------------------------------------------------------------------
__global__ void __launch_bounds__(NTHR, 1)
main_kernel(const float* __restrict__ rr,
            const float* __restrict__ ri,
            const float* __restrict__ W1,
            const float* __restrict__ b1,
            const float* __restrict__ W2,
            const float* __restrict__ b2,
            const float* __restrict__ query,
            const float* __restrict__ ipw,   // in_proj_w (192,64)
            const float* __restrict__ ipb,   // in_proj_b (192)
            const float* __restrict__ opw,   // out_proj_w (64,64)
            const float* __restrict__ opb,   // out_proj_b (64)
            float* __restrict__ out,
            int N)
{
    __shared__ float qv[64];
    __shared__ float tt[4][64];
    __shared__ float sh_u[4][64];
    // u table for the inner loop: [pair-in-lane k][sub][head], 32B per sub
    // -> for fixed k the 4 subs' addresses differ by 32B (8 banks): conflict-free
    __shared__ __align__(16) ull u_sm[8][4][4];
    __shared__ float sh_acc[NWARP][4][64];
    __shared__ float sh_s[NWARP][4];

    const int tid  = threadIdx.x;
    const int lane = tid & 31;
    const int sub  = tid & 3;                       // owns dims [sub*16, sub*16+16)
    const unsigned gmask = 0xFu << (lane & 28);     // this group's 4 lanes

    // scale = 1/sqrt(hd) * log2(e), folded into u so inner exp is bare ex2
    const float SC = 0.25f * 1.4426950408889634f;

    // ---- inline prep (every block redundantly; ~25K FMA, L2-resident) ------
    if (tid < 64) {
        float a = ipb[tid], a2 = 0.f;
        #pragma unroll 8
        for (int m = 0; m < 64; m += 2) {
            a  = fmaf(query[m],     ipw[tid * 64 + m],     a);
            a2 = fmaf(query[m + 1], ipw[tid * 64 + m + 1], a2);
        }
        qv[tid] = a + a2;
    }
    __syncthreads();
    if (tid < 256) {
        const int h = tid >> 6, j = tid & 63;
        float t = 0.f;
        #pragma unroll 8
        for (int d = 0; d < 16; d++)
            t = fmaf(qv[h * 16 + d], ipw[(64 + h * 16 + d) * 64 + j], t);
        tt[h][j] = t;
    }
    __syncthreads();
    if (tid < 256) {
        const int h = tid >> 6, j = tid & 63;
        float u = 0.f, u2 = 0.f;
        #pragma unroll 8
        for (int jj = 0; jj < 64; jj += 2) {
            u  = fmaf(tt[h][jj],     W2[jj * 64 + j],       u);
            u2 = fmaf(tt[h][jj + 1], W2[(jj + 1) * 64 + j], u2);
        }
        sh_u[h][j] = SC * (u + u2);
    }
    __syncthreads();
    if (tid < 128) {   // pack u_sm[k][sb][h] = u[h] for global pair sb*8+k
        const int k = tid >> 4, sb = (tid >> 2) & 3, h = tid & 3;
        const int gp = sb * 8 + k;
        u_sm[k][sb][h] = pk2(sh_u[h][2 * gp], sh_u[h][2 * gp + 1]);
    }
    __syncthreads();

    // ---- per-lane packed W1/b1 constants (0.5 silu factor pre-folded) -------
    ull w1ap[8], w1bp[8], b1p[8];
    #pragma unroll
    for (int k = 0; k < 8; k++) {
        const int j = sub * 16 + 2 * k;
        w1ap[k] = pk2(0.5f * W1[2 * j],     0.5f * W1[2 * j + 2]);
        w1bp[k] = pk2(0.5f * W1[2 * j + 1], 0.5f * W1[2 * j + 3]);
        b1p[k]  = pk2(0.5f * b1[j], 0.5f * b1[j + 1]);
    }

    // ---- accumulators (fixed base: w = 2^sc, softmax shift-invariant) -------
    float s4[4] = {0.f, 0.f, 0.f, 0.f};
    ull accp[4][8];
    #pragma unroll
    for (int h = 0; h < 4; h++)
        #pragma unroll
        for (int k = 0; k < 8; k++) accp[h][k] = 0ull;

    // ---- branch-free streaming loop: 1 point/group-iter, next prefetched ----
    const int gid = blockIdx.x * GPB + (tid >> 2);
    int p = gid;
    {
        const int p0 = (p < N) ? p : 0;
        float r  = __ldg(rr + p0);
        float im = __ldg(ri + p0);
        while (p < N) {
            const int pn = p + NGROUPS;
            const int pc = (pn < N) ? pn : p;      // clamped prefetch index
            const float r_n  = __ldg(rr + pc);
            const float im_n = __ldg(ri + pc);

            const ull rpk = pk2(r, r);
            const ull ipk = pk2(im, im);

            ull hid[8];
            #pragma unroll
            for (int k = 0; k < 8; k++) {
                ull hh = fma2(rpk, w1ap[k], b1p[k]);
                hh = fma2(ipk, w1bp[k], hh);
                hid[k] = silu2h(hh);
            }
            ull partp[4] = {0ull, 0ull, 0ull, 0ull};
            #pragma unroll
            for (int k = 0; k < 8; k++) {
                const ulonglong2 u01 = *(const ulonglong2*)&u_sm[k][sub][0];
                const ulonglong2 u23 = *(const ulonglong2*)&u_sm[k][sub][2];
                partp[0] = fma2(u01.x, hid[k], partp[0]);
                partp[1] = fma2(u01.y, hid[k], partp[1]);
                partp[2] = fma2(u23.x, hid[k], partp[2]);
                partp[3] = fma2(u23.y, hid[k], partp[3]);
            }
            float sc[4];
            #pragma unroll
            for (int h = 0; h < 4; h++) { float a, b; upk2(a, b, partp[h]); sc[h] = a + b; }

            // butterfly over the 4 group lanes (group-scoped mask: trip counts
            // differ by 1 across groups in the same warp)
            #pragma unroll
            for (int off = 1; off < 4; off <<= 1) {
                #pragma unroll
                for (int h = 0; h < 4; h++)
                    sc[h] += __shfl_xor_sync(gmask, sc[h], off);
            }

            #pragma unroll
            for (int h = 0; h < 4; h++) {
                const float w = ex2_ap(sc[h]);
                s4[h] += w;
                const ull wpk = pk2(w, w);
                #pragma unroll
                for (int k = 0; k < 8; k++)
                    accp[h][k] = fma2(wpk, hid[k], accp[h][k]);
            }

            p = pn; r = r_n; im = im_n;
        }
    }

    // ---- combine 8 groups of this warp (plain sums; warp reconverged) --------
    #pragma unroll
    for (int off = 4; off <= 16; off <<= 1) {
        #pragma unroll
        for (int h = 0; h < 4; h++) {
            s4[h] += __shfl_xor_sync(0xffffffffu, s4[h], off);
            #pragma unroll
            for (int k = 0; k < 8; k++) {
                float a, b; upk2(a, b, accp[h][k]);
                a += __shfl_xor_sync(0xffffffffu, a, off);
                b += __shfl_xor_sync(0xffffffffu, b, off);
                accp[h][k] = pk2(a, b);
            }
        }
    }

    // ---- block combine via shared ---------------------------------------------
    const int wid = tid >> 5;
    if (lane < 4) {
        #pragma unroll
        for (int h = 0; h < 4; h++) {
            #pragma unroll
            for (int k = 0; k < 8; k++) {
                float a, b; upk2(a, b, accp[h][k]);
                sh_acc[wid][h][lane * 16 + 2 * k]     = a;
                sh_acc[wid][h][lane * 16 + 2 * k + 1] = b;
            }
            if (lane == 0) sh_s[wid][h] = s4[h];
        }
    }
    __syncthreads();

    if (tid < 256) {
        const int h = tid >> 6;
        const int j = tid & 63;
        float A = 0.f;
        #pragma unroll
        for (int w = 0; w < NWARP; w++) A += sh_acc[w][h][j];
        g_part[blockIdx.x][h][1 + j] = A;
        if (j == 0) {
            float S = 0.f;
            #pragma unroll
            for (int w = 0; w < NWARP; w++) S += sh_s[w][h];
            g_part[blockIdx.x][h][0] = S;
        }
    }

    // ---- last block does the final combine + projections -----------------------
    __threadfence();
    __shared__ bool is_last;
    __shared__ float sh_p[4][64];
    __shared__ float sh_hbar[4][64];
    __shared__ float sh_pooled[64];
    __shared__ float sh_S[4];
    if (tid == 0) is_last = (atomicAdd(&g_done, 1) == NB - 1);
    __syncthreads();
    if (!is_last) return;
    if (tid == 0) g_done = 0;            // reset for next graph replay

    const int h = (tid >> 6) & 3;
    const int j = tid & 63;

    if (tid < 256) {
        float A = 0.f;
        #pragma unroll 4
        for (int b = 0; b < NB; b++) A += __ldg(&g_part[b][h][1 + j]);
        sh_hbar[h][j] = A;               // staging: raw acc sum
    } else if (tid < 260) {
        const int hh = tid - 256;
        float S = 0.f;
        #pragma unroll 4
        for (int b = 0; b < NB; b++) S += __ldg(&g_part[b][hh][0]);
        sh_S[hh] = S;
    }
    __syncthreads();
    if (tid < 256) sh_p[h][j] = sh_hbar[h][j] / sh_S[h];   // E[hidden] head h
    __syncthreads();

    if (tid < 256) {
        float hb = b2[j];
        #pragma unroll 8
        for (int m = 0; m < 64; m++) hb = fmaf(W2[j * 64 + m], sh_p[h][m], hb);
        sh_hbar[h][j] = hb;
    }
    __syncthreads();

    if (tid < 64) {
        const int e = tid, hh = tid >> 4;
        float pl = ipb[128 + e];
        #pragma unroll 8
        for (int jj = 0; jj < 64; jj++)
            pl = fmaf(ipw[(128 + e) * 64 + jj], sh_hbar[hh][jj], pl);
        sh_pooled[e] = pl;
    }
    __syncthreads();

    if (tid < 64) {
        float o = opb[tid];
        #pragma unroll 8
        for (int e = 0; e < 64; e++) o = fmaf(opw[tid * 64 + e], sh_pooled[e], o);
        out[tid] = o;
    }
}

// -----------------------------------------------------------------------------
extern "C" void kernel_launch(void* const* d_in, const int* in_sizes, int n_in,
                              void* d_out, int out_size)
{
    const float* rr    = (const float*)d_in[0];   // rho_real (1024*1024)
    const float* ri    = (const float*)d_in[1];   // rho_imag
    // d_in[2..5]: l_A, l_B, Z_A, Z_B — unused by the reference math
    const float* W1    = (const float*)d_in[6];   // (64,2)
    const float* b1    = (const float*)d_in[7];   // (64)
    const float* W2    = (const float*)d_in[8];   // (64,64)
    const float* b2    = (const float*)d_in[9];   // (64)
    const float* query = (const float*)d_in[10];  // (1,64)
    const float* ipw   = (const float*)d_in[11];  // (192,64)
    const float* ipb   = (const float*)d_in[12];  // (192)
    const float* opw   = (const float*)d_in[13];  // (64,64)
    const float* opb   = (const float*)d_in[14];  // (64)
    const int N = in_sizes[0];

    main_kernel<<<NB, NTHR>>>(rr, ri, W1, b1, W2, b2, query, ipw, ipb,
                              opw, opb, (float*)d_out, N);
}

// round 10
// speedup vs baseline: 1.0267x; 1.0267x over previous
#include <cuda_runtime.h>
#include <math.h>

#define NB      148              // one block per SM, single wave
#define NTHR    512              // 16 warps, 4/SMSP
#define GPB     (NTHR / 8)       // 64 groups per block
#define NGROUPS (NB * GPB)       // 9472
#define NWARP   (NTHR / 32)      // 16

typedef unsigned long long ull;

// Per-block partials: [block][head][ s, acc[64] ]  (fixed softmax base = 0;
// per-head constant score offset cancels in A/S -> dropped entirely)
__device__ float g_part[NB][4][65];
__device__ unsigned g_done = 0;

// ---- packed f32x2 helpers (ptxas never auto-fuses FFMA2) --------------------
__device__ __forceinline__ ull pk2(float lo, float hi) {
    ull r; asm("mov.b64 %0,{%1,%2};" : "=l"(r) : "f"(lo), "f"(hi)); return r;
}
__device__ __forceinline__ void upk2(float& lo, float& hi, ull p) {
    asm("mov.b64 {%0,%1},%2;" : "=f"(lo), "=f"(hi) : "l"(p));
}
__device__ __forceinline__ ull fma2(ull a, ull b, ull c) {
    ull d; asm("fma.rn.f32x2 %0,%1,%2,%3;" : "=l"(d) : "l"(a), "l"(b), "l"(c)); return d;
}
__device__ __forceinline__ float tanh_ap(float x) {
    float y; asm("tanh.approx.f32 %0,%1;" : "=f"(y) : "f"(x)); return y;
}
__device__ __forceinline__ float ex2_ap(float x) {
    float y; asm("ex2.approx.f32 %0,%1;" : "=f"(y) : "f"(x)); return y;
}
// Raw full-warp butterfly shuffle: control flow is warp-uniform by
// construction (uniform trip counts), so no WARPSYNC envelope is needed.
__device__ __forceinline__ float shflx(float v, int off) {
    float d;
    asm volatile("shfl.sync.bfly.b32 %0,%1,%2,0x1f,0xffffffff;"
                 : "=f"(d) : "f"(v), "r"(off));
    return d;
}
// silu(x) = h + h*tanh(h) with h = x/2 (the 1/2 is pre-folded into W1/b1)
__device__ __forceinline__ ull silu2h(ull hpk) {
    float h0, h1; upk2(h0, h1, hpk);
    ull tpk = pk2(tanh_ap(h0), tanh_ap(h1));
    return fma2(hpk, tpk, hpk);
}

// -----------------------------------------------------------------------------
// Single fused kernel: inline prep -> branch-free streaming exp-accumulate
// (uniform trip count, full-warp convergent, masked tail) -> block partial ->
// last block does final combine + projections.  8 lanes per point.
// -----------------------------------------------------------------------------
__global__ void __launch_bounds__(NTHR, 1)
main_kernel(const float* __restrict__ rr,
            const float* __restrict__ ri,
            const float* __restrict__ W1,
            const float* __restrict__ b1,
            const float* __restrict__ W2,
            const float* __restrict__ b2,
            const float* __restrict__ query,
            const float* __restrict__ ipw,   // in_proj_w (192,64)
            const float* __restrict__ ipb,   // in_proj_b (192)
            const float* __restrict__ opw,   // out_proj_w (64,64)
            const float* __restrict__ opb,   // out_proj_b (64)
            float* __restrict__ out,
            int N)
{
    __shared__ float qv[64];
    __shared__ float tt[4][64];
    __shared__ float sh_u[4][64];
    __shared__ float sh_acc[NWARP][4][64];
    __shared__ float sh_s[NWARP][4];

    const int tid  = threadIdx.x;
    const int lane = tid & 31;
    const int sub  = tid & 7;

    // scale = 1/sqrt(hd) * log2(e), folded into u so inner exp is bare ex2
    const float SC = 0.25f * 1.4426950408889634f;

    // ---- inline prep (every block redundantly; ~25K FMA, L2-resident) ------
    if (tid < 64) {
        float a = ipb[tid], a2 = 0.f;
        #pragma unroll 8
        for (int m = 0; m < 64; m += 2) {
            a  = fmaf(query[m],     ipw[tid * 64 + m],     a);
            a2 = fmaf(query[m + 1], ipw[tid * 64 + m + 1], a2);
        }
        qv[tid] = a + a2;
    }
    __syncthreads();
    if (tid < 256) {
        const int h = tid >> 6, j = tid & 63;
        float t = 0.f;
        #pragma unroll 8
        for (int d = 0; d < 16; d++)
            t = fmaf(qv[h * 16 + d], ipw[(64 + h * 16 + d) * 64 + j], t);
        tt[h][j] = t;
    }
    __syncthreads();
    if (tid < 256) {
        const int h = tid >> 6, j = tid & 63;
        float u = 0.f, u2 = 0.f;
        #pragma unroll 8
        for (int jj = 0; jj < 64; jj += 2) {
            u  = fmaf(tt[h][jj],     W2[jj * 64 + j],       u);
            u2 = fmaf(tt[h][jj + 1], W2[(jj + 1) * 64 + j], u2);
        }
        sh_u[h][j] = SC * (u + u2);
    }
    __syncthreads();

    // ---- per-lane packed constants (0.5 silu factor pre-folded) -------------
    const int j0 = sub * 8;
    ull w1ap[4], w1bp[4], b1p[4], u4p[4][4];
    #pragma unroll
    for (int k = 0; k < 4; k++) {
        const int j = j0 + 2 * k;
        w1ap[k] = pk2(0.5f * W1[2 * j],     0.5f * W1[2 * j + 2]);
        w1bp[k] = pk2(0.5f * W1[2 * j + 1], 0.5f * W1[2 * j + 3]);
        b1p[k]  = pk2(0.5f * b1[j], 0.5f * b1[j + 1]);
        #pragma unroll
        for (int h = 0; h < 4; h++) u4p[h][k] = pk2(sh_u[h][j], sh_u[h][j + 1]);
    }

    // ---- accumulators (fixed base: w = 2^sc, softmax shift-invariant) -------
    float s4[4] = {0.f, 0.f, 0.f, 0.f};
    ull accp[4][4];
    #pragma unroll
    for (int h = 0; h < 4; h++)
        #pragma unroll
        for (int k = 0; k < 4; k++) accp[h][k] = 0ull;

    // ---- streaming loop: UNIFORM trip count, fully warp-convergent -----------
    // Every group runs T iterations; out-of-range points are index-clamped and
    // their weight is predicated to 0 (exact: contributes nothing to s/acc).
    const int gid = blockIdx.x * GPB + (tid >> 3);
    const int T = (N + NGROUPS - 1) / NGROUPS;
    {
        int p = gid;
        int pc = (p < N) ? p : (N - 1);
        float r  = __ldg(rr + pc);
        float im = __ldg(ri + pc);
        for (int it = 0; it < T; it++) {
            const int pn = p + NGROUPS;
            const int pcn = (pn < N) ? pn : (N - 1);
            const float r_n  = __ldg(rr + pcn);
            const float im_n = __ldg(ri + pcn);
            const bool ok = (p < N);

            const ull rpk = pk2(r, r);
            const ull ipk = pk2(im, im);
            ull hid[4];
            ull partp[4] = {0ull, 0ull, 0ull, 0ull};
            #pragma unroll
            for (int k = 0; k < 4; k++) {
                ull hh = fma2(rpk, w1ap[k], b1p[k]);
                hh = fma2(ipk, w1bp[k], hh);
                hid[k] = silu2h(hh);
                #pragma unroll
                for (int h = 0; h < 4; h++)
                    partp[h] = fma2(u4p[h][k], hid[k], partp[h]);
            }
            float sc[4];
            #pragma unroll
            for (int h = 0; h < 4; h++) { float a, b; upk2(a, b, partp[h]); sc[h] = a + b; }

            // full-warp butterfly over the 8 group lanes (no WARPSYNC)
            #pragma unroll
            for (int off = 1; off < 8; off <<= 1) {
                #pragma unroll
                for (int h = 0; h < 4; h++)
                    sc[h] += shflx(sc[h], off);
            }

            #pragma unroll
            for (int h = 0; h < 4; h++) {
                const float w = ok ? ex2_ap(sc[h]) : 0.f;   // selp, no branch
                s4[h] += w;
                const ull wpk = pk2(w, w);
                #pragma unroll
                for (int k = 0; k < 4; k++)
                    accp[h][k] = fma2(wpk, hid[k], accp[h][k]);
            }

            p = pn; r = r_n; im = im_n;
        }
    }

    // ---- combine 4 groups of this warp (plain sums; warp convergent) ---------
    #pragma unroll
    for (int off = 8; off <= 16; off <<= 1) {
        #pragma unroll
        for (int h = 0; h < 4; h++) {
            s4[h] += shflx(s4[h], off);
            #pragma unroll
            for (int k = 0; k < 4; k++) {
                float a, b; upk2(a, b, accp[h][k]);
                a += shflx(a, off);
                b += shflx(b, off);
                accp[h][k] = pk2(a, b);
            }
        }
    }

    // ---- block combine via shared ---------------------------------------------
    const int wid = tid >> 5;
    if (lane < 8) {
        #pragma unroll
        for (int h = 0; h < 4; h++) {
            #pragma unroll
            for (int k = 0; k < 4; k++) {
                float a, b; upk2(a, b, accp[h][k]);
                sh_acc[wid][h][lane * 8 + 2 * k]     = a;
                sh_acc[wid][h][lane * 8 + 2 * k + 1] = b;
            }
            if (lane == 0) sh_s[wid][h] = s4[h];
        }
    }
    __syncthreads();

    if (tid < 256) {
        const int h = tid >> 6;
        const int j = tid & 63;
        float A = 0.f;
        #pragma unroll
        for (int w = 0; w < NWARP; w++) A += sh_acc[w][h][j];
        g_part[blockIdx.x][h][1 + j] = A;
        if (j == 0) {
            float S = 0.f;
            #pragma unroll
            for (int w = 0; w < NWARP; w++) S += sh_s[w][h];
            g_part[blockIdx.x][h][0] = S;
        }
    }

    // ---- last block does the final combine + projections -----------------------
    __threadfence();
    __shared__ bool is_last;
    __shared__ float sh_p[4][64];
    __shared__ float sh_hbar[4][64];
    __shared__ float sh_pooled[64];
    __shared__ float sh_S[4];
    if (tid == 0) is_last = (atomicAdd(&g_done, 1) == NB - 1);
    __syncthreads();
    if (!is_last) return;
    if (tid == 0) g_done = 0;            // reset for next graph replay

    const int h = (tid >> 6) & 3;
    const int j = tid & 63;

    if (tid < 256) {
        float A = 0.f;
        #pragma unroll 4
        for (int b = 0; b < NB; b++) A += __ldg(&g_part[b][h][1 + j]);
        sh_hbar[h][j] = A;               // staging: raw acc sum
    } else if (tid < 260) {
        const int hh = tid - 256;
        float S = 0.f;
        #pragma unroll 4
        for (int b = 0; b < NB; b++) S += __ldg(&g_part[b][hh][0]);
        sh_S[hh] = S;
    }
    __syncthreads();
    if (tid < 256) sh_p[h][j] = sh_hbar[h][j] / sh_S[h];   // E[hidden] head h
    __syncthreads();

    if (tid < 256) {
        float hb = b2[j];
        #pragma unroll 8
        for (int m = 0; m < 64; m++) hb = fmaf(W2[j * 64 + m], sh_p[h][m], hb);
        sh_hbar[h][j] = hb;
    }
    __syncthreads();

    if (tid < 64) {
        const int e = tid, hh = tid >> 4;
        float pl = ipb[128 + e];
        #pragma unroll 8
        for (int jj = 0; jj < 64; jj++)
            pl = fmaf(ipw[(128 + e) * 64 + jj], sh_hbar[hh][jj], pl);
        sh_pooled[e] = pl;
    }
    __syncthreads();

    if (tid < 64) {
        float o = opb[tid];
        #pragma unroll 8
        for (int e = 0; e < 64; e++) o = fmaf(opw[tid * 64 + e], sh_pooled[e], o);
        out[tid] = o;
    }
}

// -----------------------------------------------------------------------------
extern "C" void kernel_launch(void* const* d_in, const int* in_sizes, int n_in,
                              void* d_out, int out_size)
{
    const float* rr    = (const float*)d_in[0];   // rho_real (1024*1024)
    const float* ri    = (const float*)d_in[1];   // rho_imag
    // d_in[2..5]: l_A, l_B, Z_A, Z_B — unused by the reference math
    const float* W1    = (const float*)d_in[6];   // (64,2)
    const float* b1    = (const float*)d_in[7];   // (64)
    const float* W2    = (const float*)d_in[8];   // (64,64)
    const float* b2    = (const float*)d_in[9];   // (64)
    const float* query = (const float*)d_in[10];  // (1,64)
    const float* ipw   = (const float*)d_in[11];  // (192,64)
    const float* ipb   = (const float*)d_in[12];  // (192)
    const float* opw   = (const float*)d_in[13];  // (64,64)
    const float* opb   = (const float*)d_in[14];  // (64)
    const int N = in_sizes[0];

    main_kernel<<<NB, NTHR>>>(rr, ri, W1, b1, W2, b2, query, ipw, ipb,
                              opw, opb, (float*)d_out, N);
}